// round 1
// baseline (speedup 1.0000x reference)
#include <cuda_runtime.h>
#include <math.h>

#define D_MODEL 1024
#define SEQ     2048
#define BATCH   2
#define NH      16
#define DK      64
#define M_ROWS  (BATCH * SEQ)   // 4096

// Scratch (static device globals — no allocation allowed)
__device__ __align__(256) float g_q[BATCH * NH * SEQ * DK];   // [bh][s][dk]
__device__ __align__(256) float g_k[BATCH * NH * SEQ * DK];
__device__ __align__(256) float g_v[BATCH * NH * SEQ * DK];
__device__ __align__(256) float g_att[M_ROWS * D_MODEL];      // [b*s][h*dk]

// ---------------------------------------------------------------------------
// GEMM: dst = X @ W^T + bias.  X:[4096,1024], W:[1024,1024] (row-major, K contig)
// mode 0: scatter into heads layout [b*NH+h][s][dk];  mode 1: dst[m][n]
// Block tile 128x128, 256 threads, 8x8 per thread, K-chunk 16.
// ---------------------------------------------------------------------------
__global__ void __launch_bounds__(256, 2) gemm_bias_kernel(
    const float* __restrict__ X, const float* __restrict__ W,
    const float* __restrict__ bias, float* __restrict__ dst, int mode)
{
    __shared__ float Xs[16][132];   // [k][m], pad 132 keeps 16B alignment
    __shared__ float Ws[16][132];   // [k][n]

    const int tid = threadIdx.x;
    const int tx  = tid & 15;
    const int ty  = tid >> 4;
    const int m0  = blockIdx.y * 128;
    const int n0  = blockIdx.x * 128;

    float acc[8][8] = {};

    for (int k0 = 0; k0 < D_MODEL; k0 += 16) {
        __syncthreads();
#pragma unroll
        for (int i = 0; i < 2; i++) {
            int li = tid + i * 256;          // 0..511
            int r  = li >> 2;                // 0..127
            int kq = (li & 3) << 2;          // 0,4,8,12
            float4 xv = *(const float4*)(X + (size_t)(m0 + r) * D_MODEL + k0 + kq);
            Xs[kq + 0][r] = xv.x; Xs[kq + 1][r] = xv.y;
            Xs[kq + 2][r] = xv.z; Xs[kq + 3][r] = xv.w;
            float4 wv = *(const float4*)(W + (size_t)(n0 + r) * D_MODEL + k0 + kq);
            Ws[kq + 0][r] = wv.x; Ws[kq + 1][r] = wv.y;
            Ws[kq + 2][r] = wv.z; Ws[kq + 3][r] = wv.w;
        }
        __syncthreads();
#pragma unroll
        for (int kk = 0; kk < 16; kk++) {
            float4 a0 = *(const float4*)&Xs[kk][ty * 8];
            float4 a1 = *(const float4*)&Xs[kk][ty * 8 + 4];
            float4 b0 = *(const float4*)&Ws[kk][tx * 8];
            float4 b1 = *(const float4*)&Ws[kk][tx * 8 + 4];
            float a[8] = {a0.x, a0.y, a0.z, a0.w, a1.x, a1.y, a1.z, a1.w};
            float b[8] = {b0.x, b0.y, b0.z, b0.w, b1.x, b1.y, b1.z, b1.w};
#pragma unroll
            for (int i = 0; i < 8; i++)
#pragma unroll
                for (int j = 0; j < 8; j++)
                    acc[i][j] = fmaf(a[i], b[j], acc[i][j]);
        }
    }

#pragma unroll
    for (int i = 0; i < 8; i++) {
        int m = m0 + ty * 8 + i;
#pragma unroll
        for (int j = 0; j < 8; j++) {
            int n = n0 + tx * 8 + j;
            float v = acc[i][j] + bias[n];
            if (mode == 0) {
                int b = m >> 11;            // batch (m / 2048)
                int s = m & 2047;
                int h = n >> 6;             // head
                int d = n & 63;
                dst[(((size_t)(b * NH + h)) * SEQ + s) * DK + d] = v;
            } else {
                dst[(size_t)m * D_MODEL + n] = v;
            }
        }
    }
}

// ---------------------------------------------------------------------------
// Flash attention: block = (bh, q-tile of 64). Online softmax over 32 KV tiles.
// Thread layout 16x16, 4x4 per-thread fragments for S and O.
// Dynamic smem: Qs[64][68] (pre-scaled, [d][q]), KPs[64][68] (K as [d][k],
// reused as P [k][q]), Vs[64][68] ([k][d]).
// ---------------------------------------------------------------------------
#define SPAD 68

__global__ void __launch_bounds__(256) attn_kernel()
{
    extern __shared__ float sm[];
    float* Qs  = sm;                   // [64][SPAD]  [d][q]
    float* KPs = sm + 64 * SPAD;       // [64][SPAD]  K:[d][k] then P:[k][q]
    float* Vs  = sm + 2 * 64 * SPAD;   // [64][SPAD]  [k][d]

    const int tid = threadIdx.x;
    const int tx  = tid & 15;
    const int ty  = tid >> 4;
    const int qt  = blockIdx.x;        // 0..31
    const int bh  = blockIdx.y;        // 0..31
    const float scale = 0.125f;        // 1/sqrt(64)

    const float* Qg = g_q + (size_t)bh * SEQ * DK;
    const float* Kg = g_k + (size_t)bh * SEQ * DK;
    const float* Vg = g_v + (size_t)bh * SEQ * DK;

    // Load Q tile transposed, pre-scaled
#pragma unroll
    for (int r = 0; r < 4; r++) {
        int q = r * 16 + ty;
        int d = tx * 4;
        float4 v = *(const float4*)(Qg + (size_t)(qt * 64 + q) * DK + d);
        Qs[(d + 0) * SPAD + q] = v.x * scale;
        Qs[(d + 1) * SPAD + q] = v.y * scale;
        Qs[(d + 2) * SPAD + q] = v.z * scale;
        Qs[(d + 3) * SPAD + q] = v.w * scale;
    }

    float O[4][4] = {};
    float mrow[4] = {-INFINITY, -INFINITY, -INFINITY, -INFINITY};
    float lrow[4] = {};

    for (int kt = 0; kt < SEQ / 64; kt++) {
        __syncthreads();   // prior PV reads done (and Q visible on iter 0)
#pragma unroll
        for (int r = 0; r < 4; r++) {
            int k = r * 16 + ty;
            int d = tx * 4;
            float4 kv = *(const float4*)(Kg + (size_t)(kt * 64 + k) * DK + d);
            KPs[(d + 0) * SPAD + k] = kv.x;
            KPs[(d + 1) * SPAD + k] = kv.y;
            KPs[(d + 2) * SPAD + k] = kv.z;
            KPs[(d + 3) * SPAD + k] = kv.w;
            float4 vv = *(const float4*)(Vg + (size_t)(kt * 64 + k) * DK + d);
            *(float4*)&Vs[k * SPAD + d] = vv;
        }
        __syncthreads();

        // S[i][j] = sum_d Q[q][d] * K[k][d]   (scale already in Q)
        float S[4][4] = {};
#pragma unroll 16
        for (int d = 0; d < 64; d++) {
            float4 a = *(const float4*)&Qs[d * SPAD + ty * 4];
            float4 b = *(const float4*)&KPs[d * SPAD + tx * 4];
            float av[4] = {a.x, a.y, a.z, a.w};
            float bv[4] = {b.x, b.y, b.z, b.w};
#pragma unroll
            for (int i = 0; i < 4; i++)
#pragma unroll
                for (int j = 0; j < 4; j++)
                    S[i][j] = fmaf(av[i], bv[j], S[i][j]);
        }

        // Online softmax update
#pragma unroll
        for (int i = 0; i < 4; i++) {
            float rm = fmaxf(fmaxf(S[i][0], S[i][1]), fmaxf(S[i][2], S[i][3]));
#pragma unroll
            for (int off = 8; off; off >>= 1)
                rm = fmaxf(rm, __shfl_xor_sync(0xffffffffu, rm, off));
            float mnew = fmaxf(mrow[i], rm);
            float c = __expf(mrow[i] - mnew);   // 0 on first tile (-inf)
            mrow[i] = mnew;
            float rs = 0.f;
#pragma unroll
            for (int j = 0; j < 4; j++) {
                S[i][j] = __expf(S[i][j] - mnew);
                rs += S[i][j];
            }
#pragma unroll
            for (int off = 8; off; off >>= 1)
                rs += __shfl_xor_sync(0xffffffffu, rs, off);
            lrow[i] = lrow[i] * c + rs;
#pragma unroll
            for (int j = 0; j < 4; j++) O[i][j] *= c;
        }

        __syncthreads();   // all S reads of K done -> reuse KPs for P
#pragma unroll
        for (int i = 0; i < 4; i++)
#pragma unroll
            for (int j = 0; j < 4; j++)
                KPs[(tx * 4 + j) * SPAD + (ty * 4 + i)] = S[i][j];
        __syncthreads();

        // O[q][dv] += sum_k P[k][q] * V[k][dv]
#pragma unroll 16
        for (int k = 0; k < 64; k++) {
            float4 a = *(const float4*)&KPs[k * SPAD + ty * 4];
            float4 b = *(const float4*)&Vs[k * SPAD + tx * 4];
            float av[4] = {a.x, a.y, a.z, a.w};
            float bv[4] = {b.x, b.y, b.z, b.w};
#pragma unroll
            for (int i = 0; i < 4; i++)
#pragma unroll
                for (int j = 0; j < 4; j++)
                    O[i][j] = fmaf(av[i], bv[j], O[i][j]);
        }
    }

    // Normalize and write combined layout [b*s][h*dk]
    int b = bh >> 4, h = bh & 15;
#pragma unroll
    for (int i = 0; i < 4; i++) {
        float inv = 1.0f / lrow[i];
        int q = qt * 64 + ty * 4 + i;
        size_t base = ((size_t)b * SEQ + q) * D_MODEL + h * DK + tx * 4;
#pragma unroll
        for (int j = 0; j < 4; j++)
            g_att[base + j] = O[i][j] * inv;
    }
}

// ---------------------------------------------------------------------------
extern "C" void kernel_launch(void* const* d_in, const int* in_sizes, int n_in,
                              void* d_out, int out_size)
{
    const float* query = (const float*)d_in[0];
    const float* key   = (const float*)d_in[1];
    const float* value = (const float*)d_in[2];
    const float* Wq    = (const float*)d_in[3];
    const float* bq    = (const float*)d_in[4];
    const float* Wk    = (const float*)d_in[5];
    const float* bk    = (const float*)d_in[6];
    const float* Wv    = (const float*)d_in[7];
    const float* bv    = (const float*)d_in[8];
    const float* Wo    = (const float*)d_in[9];
    const float* bo    = (const float*)d_in[10];

    float *qp, *kp, *vp, *ap;
    cudaGetSymbolAddress((void**)&qp, g_q);
    cudaGetSymbolAddress((void**)&kp, g_k);
    cudaGetSymbolAddress((void**)&vp, g_v);
    cudaGetSymbolAddress((void**)&ap, g_att);

    dim3 ggrid(D_MODEL / 128, M_ROWS / 128);   // (8, 32)
    gemm_bias_kernel<<<ggrid, 256>>>(query, Wq, bq, qp, 0);
    gemm_bias_kernel<<<ggrid, 256>>>(key,   Wk, bk, kp, 0);
    gemm_bias_kernel<<<ggrid, 256>>>(value, Wv, bv, vp, 0);

    int smem_attn = 3 * 64 * SPAD * sizeof(float);   // 52224 bytes
    cudaFuncSetAttribute(attn_kernel, cudaFuncAttributeMaxDynamicSharedMemorySize,
                         smem_attn);
    attn_kernel<<<dim3(SEQ / 64, BATCH * NH), 256, smem_attn>>>();

    gemm_bias_kernel<<<ggrid, 256>>>(ap, Wo, bo, (float*)d_out, 1);
}

// round 4
// speedup vs baseline: 3.9392x; 3.9392x over previous
#include <cuda_runtime.h>
#include <cuda_fp16.h>
#include <math.h>
#include <stdint.h>

#define D_MODEL 1024
#define SEQ     2048
#define BATCH   2
#define NH      16
#define DK      64
#define M_ROWS  (BATCH * SEQ)          // 4096
#define QSCALE  (0.125f * 1.44269504088896f)   // 1/sqrt(64) * log2(e)

// ---------------- scratch (static device globals; no allocation) ------------
__device__ __align__(256) __half g_xqh[M_ROWS * D_MODEL];
__device__ __align__(256) __half g_xql[M_ROWS * D_MODEL];
__device__ __align__(256) __half g_xkh[M_ROWS * D_MODEL];
__device__ __align__(256) __half g_xkl[M_ROWS * D_MODEL];
__device__ __align__(256) __half g_xvh[M_ROWS * D_MODEL];
__device__ __align__(256) __half g_xvl[M_ROWS * D_MODEL];
__device__ __align__(256) __half g_wqh[D_MODEL * D_MODEL];
__device__ __align__(256) __half g_wql[D_MODEL * D_MODEL];
__device__ __align__(256) __half g_wkh[D_MODEL * D_MODEL];
__device__ __align__(256) __half g_wkl[D_MODEL * D_MODEL];
__device__ __align__(256) __half g_wvh[D_MODEL * D_MODEL];
__device__ __align__(256) __half g_wvl[D_MODEL * D_MODEL];
__device__ __align__(256) __half g_woh[D_MODEL * D_MODEL];
__device__ __align__(256) __half g_wol[D_MODEL * D_MODEL];
__device__ __align__(256) __half g_qh[BATCH * NH * SEQ * DK];   // [bh][s][dk], pre-scaled
__device__ __align__(256) __half g_kh[BATCH * NH * SEQ * DK];
__device__ __align__(256) __half g_vh[BATCH * NH * SEQ * DK];
__device__ __align__(256) __half g_vl[BATCH * NH * SEQ * DK];
__device__ __align__(256) __half g_ah[M_ROWS * D_MODEL];        // attn out hi
__device__ __align__(256) __half g_al[M_ROWS * D_MODEL];        // attn out lo

// ---------------- PTX helpers (base sm_80+ ISA only — compiles at sm_103) ---
__device__ __forceinline__ uint32_t smem_u32(const void* p) {
    uint32_t a;
    asm("{ .reg .u64 t; cvta.to.shared.u64 t, %1; cvt.u32.u64 %0, t; }"
        : "=r"(a) : "l"(p));
    return a;
}
#define SWZ128(off) ((off) ^ (((off) >> 3) & 0x70))

__device__ __forceinline__ uint32_t h2_as_u32(__half2 h) {
    union { __half2 h; uint32_t u; } c;
    c.h = h;
    return c.u;
}

__device__ __forceinline__ void cp_async16(uint32_t smem, const void* gmem) {
    asm volatile("cp.async.cg.shared.global [%0], [%1], 16;"
                 :: "r"(smem), "l"(gmem) : "memory");
}
#define CP_COMMIT() asm volatile("cp.async.commit_group;" ::: "memory")
#define CP_WAIT_1() asm volatile("cp.async.wait_group 1;" ::: "memory")
#define CP_WAIT_0() asm volatile("cp.async.wait_group 0;" ::: "memory")

__device__ __forceinline__ void ldsm4(uint32_t* r, uint32_t a) {
    asm volatile("ldmatrix.sync.aligned.m8n8.x4.shared.b16 {%0,%1,%2,%3}, [%4];"
                 : "=r"(r[0]), "=r"(r[1]), "=r"(r[2]), "=r"(r[3]) : "r"(a));
}
__device__ __forceinline__ void ldsm4t(uint32_t* r, uint32_t a) {
    asm volatile("ldmatrix.sync.aligned.m8n8.x4.trans.shared.b16 {%0,%1,%2,%3}, [%4];"
                 : "=r"(r[0]), "=r"(r[1]), "=r"(r[2]), "=r"(r[3]) : "r"(a));
}
__device__ __forceinline__ void mma16816(float* c, const uint32_t* a, const uint32_t* b) {
    asm volatile(
        "mma.sync.aligned.m16n8k16.row.col.f32.f16.f16.f32 "
        "{%0,%1,%2,%3},{%4,%5,%6,%7},{%8,%9},{%0,%1,%2,%3};"
        : "+f"(c[0]), "+f"(c[1]), "+f"(c[2]), "+f"(c[3])
        : "r"(a[0]), "r"(a[1]), "r"(a[2]), "r"(a[3]), "r"(b[0]), "r"(b[1]));
}

// ---------------- fp32 -> (fp16 hi, fp16 lo) split ---------------------------
__global__ void cvt_split(const float* __restrict__ s, __half* __restrict__ hi,
                          __half* __restrict__ lo, int n4) {
    int i = blockIdx.x * blockDim.x + threadIdx.x;
    if (i >= n4) return;
    float4 v = ((const float4*)s)[i];
    __half h0 = __float2half_rn(v.x), h1 = __float2half_rn(v.y);
    __half h2 = __float2half_rn(v.z), h3 = __float2half_rn(v.w);
    ((__half2*)hi)[2 * i + 0] = __halves2half2(h0, h1);
    ((__half2*)hi)[2 * i + 1] = __halves2half2(h2, h3);
    ((__half2*)lo)[2 * i + 0] = __halves2half2(
        __float2half_rn(v.x - __half2float(h0)), __float2half_rn(v.y - __half2float(h1)));
    ((__half2*)lo)[2 * i + 1] = __halves2half2(
        __float2half_rn(v.z - __half2float(h2)), __float2half_rn(v.w - __half2float(h3)));
}

// ---------------- HMMA GEMM: dst = (Xh+Xl) @ (Wh+Wl)^T + bias (3-term) ------
// A:[4096,1024] fp16, B:[1024,1024] fp16, both K-contiguous. BM=BN=128, BK=64.
// mode 0: Q -> g_qh (heads, scaled)   1: K -> g_kh   2: V -> g_vh/g_vl
// mode 3: fp32 row-major to dst
#define GSTAGE_B 32768                        // A 16KB + B 16KB per stage
#define GEMM_SMEM (2 * GSTAGE_B)              // 64KB

__device__ __forceinline__ void g_ldtile(const __half* __restrict__ Ap,
                                         const __half* __restrict__ Bp,
                                         uint32_t sA, uint32_t sB, int tid) {
#pragma unroll
    for (int i = 0; i < 4; i++) {
        int c = i * 256 + tid;
        int row = c >> 3, q = c & 7;
        cp_async16(sA + SWZ128((uint32_t)(row * 128 + q * 16)),
                   Ap + (size_t)row * D_MODEL + q * 8);
    }
#pragma unroll
    for (int i = 0; i < 4; i++) {
        int c = i * 256 + tid;
        int row = c >> 3, q = c & 7;
        cp_async16(sB + SWZ128((uint32_t)(row * 128 + q * 16)),
                   Bp + (size_t)row * D_MODEL + q * 8);
    }
}

__global__ void __launch_bounds__(256, 2) gemm_hmma(
    const __half* __restrict__ Ah, const __half* __restrict__ Al,
    const __half* __restrict__ Bh, const __half* __restrict__ Bl,
    const float* __restrict__ bias, void* __restrict__ dst, int mode)
{
    extern __shared__ char smem[];
    const uint32_t sbase = smem_u32(smem);
    const int tid = threadIdx.x;
    const int lane = tid & 31;
    const int wid = tid >> 5;
    const int wm = (wid >> 2) * 64;       // warp m offset in tile
    const int wn = (wid & 3) * 32;        // warp n offset in tile
    const int m0 = blockIdx.y * 128;
    const int n0 = blockIdx.x * 128;

    const __half* Aps[3] = {Ah, Ah, Al};
    const __half* Bps[3] = {Bh, Bl, Bh};

    float acc[4][4][4] = {};

    // prologue
    g_ldtile(Aps[0] + (size_t)m0 * D_MODEL, Bps[0] + (size_t)n0 * D_MODEL,
             sbase, sbase + 16384, tid);
    CP_COMMIT();

    const int NG = 48;   // 3 phases x 16 k-iters
    for (int g = 0; g < NG; g++) {
        if (g + 1 < NG) {
            int ph = (g + 1) >> 4, kk0 = ((g + 1) & 15) * 64;
            uint32_t sb = sbase + ((g + 1) & 1) * GSTAGE_B;
            g_ldtile(Aps[ph] + (size_t)m0 * D_MODEL + kk0,
                     Bps[ph] + (size_t)n0 * D_MODEL + kk0, sb, sb + 16384, tid);
        }
        CP_COMMIT();
        CP_WAIT_1();
        __syncthreads();

        uint32_t sA = sbase + (g & 1) * GSTAGE_B;
        uint32_t sB = sA + 16384;
#pragma unroll
        for (int kk = 0; kk < 4; kk++) {
            uint32_t aF[4][4], bF[2][4];
#pragma unroll
            for (int mt = 0; mt < 4; mt++) {
                int row = wm + mt * 16 + (lane & 15);
                int kh = (lane >> 4);
                ldsm4(aF[mt], sA + SWZ128((uint32_t)(row * 128 + (kk * 16 + kh * 8) * 2)));
            }
#pragma unroll
            for (int p = 0; p < 2; p++) {
                int row = wn + p * 16 + ((lane >> 4) << 3) + (lane & 7);
                int kh = (lane >> 3) & 1;
                ldsm4(bF[p], sB + SWZ128((uint32_t)(row * 128 + (kk * 16 + kh * 8) * 2)));
            }
#pragma unroll
            for (int mt = 0; mt < 4; mt++)
#pragma unroll
                for (int nt = 0; nt < 4; nt++)
                    mma16816(acc[mt][nt], aF[mt], &bF[nt >> 1][(nt & 1) * 2]);
        }
        __syncthreads();
    }

    // epilogue
#pragma unroll
    for (int mt = 0; mt < 4; mt++) {
#pragma unroll
        for (int nt = 0; nt < 4; nt++) {
            int m = m0 + wm + mt * 16 + (lane >> 2);
            int n = n0 + wn + nt * 8 + 2 * (lane & 3);
            float b0 = bias[n], b1 = bias[n + 1];
#pragma unroll
            for (int half = 0; half < 2; half++) {
                int mm = m + half * 8;
                float v0 = acc[mt][nt][half * 2 + 0] + b0;
                float v1 = acc[mt][nt][half * 2 + 1] + b1;
                if (mode == 3) {
                    float2 o = {v0, v1};
                    *(float2*)((float*)dst + (size_t)mm * D_MODEL + n) = o;
                } else {
                    int b = mm >> 11, s = mm & 2047;
                    int h = n >> 6, dd = n & 63;
                    size_t idx = (((size_t)(b * NH + h)) * SEQ + s) * DK + dd;
                    if (mode == 0) {
                        *(__half2*)(g_qh + idx) =
                            __halves2half2(__float2half_rn(v0 * QSCALE),
                                           __float2half_rn(v1 * QSCALE));
                    } else if (mode == 1) {
                        *(__half2*)(g_kh + idx) =
                            __halves2half2(__float2half_rn(v0), __float2half_rn(v1));
                    } else {
                        __half h0 = __float2half_rn(v0), h1 = __float2half_rn(v1);
                        *(__half2*)(g_vh + idx) = __halves2half2(h0, h1);
                        *(__half2*)(g_vl + idx) = __halves2half2(
                            __float2half_rn(v0 - __half2float(h0)),
                            __float2half_rn(v1 - __half2float(h1)));
                    }
                }
            }
        }
    }
}

// ---------------- flash attention on mma.sync --------------------------------
// block = (qt in 0..15 [128 q rows], bh in 0..31). 256 threads, 8 warps,
// warp owns 16 q rows. KV tiles of 64 keys, double-buffered cp.async.
// smem: Q[128][64]h (16KB) + 2 stages x { K[64][64], Vh[64][64], Vl[64][64] } (24KB each)
#define ASTAGE_B 24576
#define ATTN_SMEM (16384 + 2 * ASTAGE_B)      // 64KB

__device__ __forceinline__ void a_ldkv(const __half* __restrict__ Kg,
                                       const __half* __restrict__ Vhg,
                                       const __half* __restrict__ Vlg,
                                       int kt, uint32_t sK, int tid) {
#pragma unroll
    for (int i = 0; i < 2; i++) {
        int c = i * 256 + tid;                 // 0..511
        int row = c >> 3, q = c & 7;
        uint32_t so = SWZ128((uint32_t)(row * 128 + q * 16));
        size_t go = (size_t)(kt * 64 + row) * DK + q * 8;
        cp_async16(sK + so, Kg + go);
        cp_async16(sK + 8192 + so, Vhg + go);
        cp_async16(sK + 16384 + so, Vlg + go);
    }
}

__global__ void __launch_bounds__(256, 2) attn_hmma()
{
    extern __shared__ char smem[];
    const uint32_t sbase = smem_u32(smem);
    const uint32_t sQ = sbase;
    const int tid = threadIdx.x;
    const int lane = tid & 31;
    const int wid = tid >> 5;
    const int qt = blockIdx.x;
    const int bh = blockIdx.y;
    const int m0 = wid * 16;                  // warp's q rows within tile

    const __half* Qg  = g_qh + (size_t)bh * SEQ * DK;
    const __half* Kg  = g_kh + (size_t)bh * SEQ * DK;
    const __half* Vhg = g_vh + (size_t)bh * SEQ * DK;
    const __half* Vlg = g_vl + (size_t)bh * SEQ * DK;

    // load Q tile (group 0 together with KV tile 0)
#pragma unroll
    for (int i = 0; i < 4; i++) {
        int c = i * 256 + tid;                 // 0..1023
        int row = c >> 3, q = c & 7;
        cp_async16(sQ + SWZ128((uint32_t)(row * 128 + q * 16)),
                   Qg + (size_t)(qt * 128 + row) * DK + q * 8);
    }
    a_ldkv(Kg, Vhg, Vlg, 0, sbase + 16384, tid);
    CP_COMMIT();

    float oc[8][4] = {};
    float mst0 = -INFINITY, mst1 = -INFINITY;
    float lst0 = 0.f, lst1 = 0.f;

    for (int kt = 0; kt < SEQ / 64; kt++) {
        if (kt + 1 < SEQ / 64)
            a_ldkv(Kg, Vhg, Vlg, kt + 1, sbase + 16384 + ((kt + 1) & 1) * ASTAGE_B, tid);
        CP_COMMIT();
        CP_WAIT_1();
        __syncthreads();

        uint32_t sK = sbase + 16384 + (kt & 1) * ASTAGE_B;
        uint32_t sVh = sK + 8192, sVl = sK + 16384;

        // S = Qscaled @ K^T   (8 n-tiles of 8 keys)
        float sc[8][4] = {};
#pragma unroll
        for (int kk = 0; kk < 4; kk++) {
            uint32_t aQ[4], bK[4][4];
            {
                int row = m0 + (lane & 15);
                int kh = lane >> 4;
                ldsm4(aQ, sQ + SWZ128((uint32_t)(row * 128 + (kk * 16 + kh * 8) * 2)));
            }
#pragma unroll
            for (int p = 0; p < 4; p++) {
                int row = p * 16 + ((lane >> 4) << 3) + (lane & 7);
                int kh = (lane >> 3) & 1;
                ldsm4(bK[p], sK + SWZ128((uint32_t)(row * 128 + (kk * 16 + kh * 8) * 2)));
            }
#pragma unroll
            for (int nt = 0; nt < 8; nt++)
                mma16816(sc[nt], aQ, &bK[nt >> 1][(nt & 1) * 2]);
        }

        // online softmax (log2 domain; scale pre-folded into Q)
        float mx0 = -INFINITY, mx1 = -INFINITY;
#pragma unroll
        for (int t = 0; t < 8; t++) {
            mx0 = fmaxf(mx0, fmaxf(sc[t][0], sc[t][1]));
            mx1 = fmaxf(mx1, fmaxf(sc[t][2], sc[t][3]));
        }
        mx0 = fmaxf(mx0, __shfl_xor_sync(0xffffffffu, mx0, 1));
        mx0 = fmaxf(mx0, __shfl_xor_sync(0xffffffffu, mx0, 2));
        mx1 = fmaxf(mx1, __shfl_xor_sync(0xffffffffu, mx1, 1));
        mx1 = fmaxf(mx1, __shfl_xor_sync(0xffffffffu, mx1, 2));
        float mn0 = fmaxf(mst0, mx0), mn1 = fmaxf(mst1, mx1);
        float c0 = exp2f(mst0 - mn0), c1 = exp2f(mst1 - mn1);
        mst0 = mn0; mst1 = mn1;
        float sum0 = 0.f, sum1 = 0.f;
#pragma unroll
        for (int t = 0; t < 8; t++) {
            sc[t][0] = exp2f(sc[t][0] - mn0); sum0 += sc[t][0];
            sc[t][1] = exp2f(sc[t][1] - mn0); sum0 += sc[t][1];
            sc[t][2] = exp2f(sc[t][2] - mn1); sum1 += sc[t][2];
            sc[t][3] = exp2f(sc[t][3] - mn1); sum1 += sc[t][3];
        }
        sum0 += __shfl_xor_sync(0xffffffffu, sum0, 1);
        sum0 += __shfl_xor_sync(0xffffffffu, sum0, 2);
        sum1 += __shfl_xor_sync(0xffffffffu, sum1, 1);
        sum1 += __shfl_xor_sync(0xffffffffu, sum1, 2);
        lst0 = lst0 * c0 + sum0;
        lst1 = lst1 * c1 + sum1;
#pragma unroll
        for (int t = 0; t < 8; t++) {
            oc[t][0] *= c0; oc[t][1] *= c0;
            oc[t][2] *= c1; oc[t][3] *= c1;
        }

        // O += P @ (Vh + Vl)
#pragma unroll
        for (int kk = 0; kk < 4; kk++) {
            uint32_t pa[4];
            pa[0] = h2_as_u32(__floats2half2_rn(sc[2*kk][0],   sc[2*kk][1]));
            pa[1] = h2_as_u32(__floats2half2_rn(sc[2*kk][2],   sc[2*kk][3]));
            pa[2] = h2_as_u32(__floats2half2_rn(sc[2*kk+1][0], sc[2*kk+1][1]));
            pa[3] = h2_as_u32(__floats2half2_rn(sc[2*kk+1][2], sc[2*kk+1][3]));
            uint32_t bV[4][4];
#pragma unroll
            for (int p = 0; p < 4; p++) {
                int krow = kk * 16 + ((lane >> 3) & 1) * 8 + (lane & 7);
                int ncol = p * 16 + ((lane >> 4) << 3);
                ldsm4t(bV[p], sVh + SWZ128((uint32_t)(krow * 128 + ncol * 2)));
            }
#pragma unroll
            for (int nt = 0; nt < 8; nt++)
                mma16816(oc[nt], pa, &bV[nt >> 1][(nt & 1) * 2]);
#pragma unroll
            for (int p = 0; p < 4; p++) {
                int krow = kk * 16 + ((lane >> 3) & 1) * 8 + (lane & 7);
                int ncol = p * 16 + ((lane >> 4) << 3);
                ldsm4t(bV[p], sVl + SWZ128((uint32_t)(krow * 128 + ncol * 2)));
            }
#pragma unroll
            for (int nt = 0; nt < 8; nt++)
                mma16816(oc[nt], pa, &bV[nt >> 1][(nt & 1) * 2]);
        }
        __syncthreads();
    }

    // normalize, split hi/lo, write combined layout [b*s][h*64+dv]
    const int b = bh >> 4, h = bh & 15;
    const float inv0 = 1.0f / lst0, inv1 = 1.0f / lst1;
#pragma unroll
    for (int t = 0; t < 8; t++) {
        int dv = t * 8 + 2 * (lane & 3);
#pragma unroll
        for (int half = 0; half < 2; half++) {
            int r = qt * 128 + m0 + (lane >> 2) + half * 8;
            float inv = half ? inv1 : inv0;
            float v0 = oc[t][half * 2 + 0] * inv;
            float v1 = oc[t][half * 2 + 1] * inv;
            __half h0 = __float2half_rn(v0), h1 = __float2half_rn(v1);
            size_t idx = ((size_t)b * SEQ + r) * D_MODEL + h * DK + dv;
            *(__half2*)(g_ah + idx) = __halves2half2(h0, h1);
            *(__half2*)(g_al + idx) = __halves2half2(
                __float2half_rn(v0 - __half2float(h0)),
                __float2half_rn(v1 - __half2float(h1)));
        }
    }
}

// ---------------------------------------------------------------------------
extern "C" void kernel_launch(void* const* d_in, const int* in_sizes, int n_in,
                              void* d_out, int out_size)
{
    const float* query = (const float*)d_in[0];
    const float* key   = (const float*)d_in[1];
    const float* value = (const float*)d_in[2];
    const float* Wq    = (const float*)d_in[3];
    const float* bq    = (const float*)d_in[4];
    const float* Wk    = (const float*)d_in[5];
    const float* bk    = (const float*)d_in[6];
    const float* Wv    = (const float*)d_in[7];
    const float* bv    = (const float*)d_in[8];
    const float* Wo    = (const float*)d_in[9];
    const float* bo    = (const float*)d_in[10];

    __half *xqh, *xql, *xkh, *xkl, *xvh, *xvl;
    __half *wqh, *wql, *wkh, *wkl, *wvh, *wvl, *woh, *wol;
    __half *ah, *al;
    cudaGetSymbolAddress((void**)&xqh, g_xqh);
    cudaGetSymbolAddress((void**)&xql, g_xql);
    cudaGetSymbolAddress((void**)&xkh, g_xkh);
    cudaGetSymbolAddress((void**)&xkl, g_xkl);
    cudaGetSymbolAddress((void**)&xvh, g_xvh);
    cudaGetSymbolAddress((void**)&xvl, g_xvl);
    cudaGetSymbolAddress((void**)&wqh, g_wqh);
    cudaGetSymbolAddress((void**)&wql, g_wql);
    cudaGetSymbolAddress((void**)&wkh, g_wkh);
    cudaGetSymbolAddress((void**)&wkl, g_wkl);
    cudaGetSymbolAddress((void**)&wvh, g_wvh);
    cudaGetSymbolAddress((void**)&wvl, g_wvl);
    cudaGetSymbolAddress((void**)&woh, g_woh);
    cudaGetSymbolAddress((void**)&wol, g_wol);
    cudaGetSymbolAddress((void**)&ah, g_ah);
    cudaGetSymbolAddress((void**)&al, g_al);

    const int nx4 = M_ROWS * D_MODEL / 4;
    const int nw4 = D_MODEL * D_MODEL / 4;
    cvt_split<<<nx4 / 256, 256>>>(query, xqh, xql, nx4);
    cvt_split<<<nx4 / 256, 256>>>(key,   xkh, xkl, nx4);
    cvt_split<<<nx4 / 256, 256>>>(value, xvh, xvl, nx4);
    cvt_split<<<nw4 / 256, 256>>>(Wq, wqh, wql, nw4);
    cvt_split<<<nw4 / 256, 256>>>(Wk, wkh, wkl, nw4);
    cvt_split<<<nw4 / 256, 256>>>(Wv, wvh, wvl, nw4);
    cvt_split<<<nw4 / 256, 256>>>(Wo, woh, wol, nw4);

    cudaFuncSetAttribute(gemm_hmma, cudaFuncAttributeMaxDynamicSharedMemorySize,
                         GEMM_SMEM);
    cudaFuncSetAttribute(attn_hmma, cudaFuncAttributeMaxDynamicSharedMemorySize,
                         ATTN_SMEM);

    dim3 ggrid(D_MODEL / 128, M_ROWS / 128);   // (8, 32)
    gemm_hmma<<<ggrid, 256, GEMM_SMEM>>>(xqh, xql, wqh, wql, bq, nullptr, 0);
    gemm_hmma<<<ggrid, 256, GEMM_SMEM>>>(xkh, xkl, wkh, wkl, bk, nullptr, 1);
    gemm_hmma<<<ggrid, 256, GEMM_SMEM>>>(xvh, xvl, wvh, wvl, bv, nullptr, 2);

    attn_hmma<<<dim3(SEQ / 128, BATCH * NH), 256, ATTN_SMEM>>>();

    gemm_hmma<<<ggrid, 256, GEMM_SMEM>>>(ah, al, woh, wol, bo, d_out, 3);
}

// round 5
// speedup vs baseline: 5.6006x; 1.4218x over previous
#include <cuda_runtime.h>
#include <cuda_fp16.h>
#include <math.h>
#include <stdint.h>

#define D_MODEL 1024
#define SEQ     2048
#define BATCH   2
#define NH      16
#define DK      64
#define M_ROWS  (BATCH * SEQ)          // 4096
#define QSCALE  (0.125f * 1.44269504088896f)   // 1/sqrt(64) * log2(e)

// ---------------- scratch (static device globals; no allocation) ------------
__device__ __align__(256) __half g_xq[M_ROWS * D_MODEL];        // fp16(X) inputs
__device__ __align__(256) __half g_xk[M_ROWS * D_MODEL];
__device__ __align__(256) __half g_xv[M_ROWS * D_MODEL];
__device__ __align__(256) __half g_wqh[D_MODEL * D_MODEL];      // weight hi/lo
__device__ __align__(256) __half g_wql[D_MODEL * D_MODEL];
__device__ __align__(256) __half g_wkh[D_MODEL * D_MODEL];
__device__ __align__(256) __half g_wkl[D_MODEL * D_MODEL];
__device__ __align__(256) __half g_wvh[D_MODEL * D_MODEL];
__device__ __align__(256) __half g_wvl[D_MODEL * D_MODEL];
__device__ __align__(256) __half g_woh[D_MODEL * D_MODEL];
__device__ __align__(256) __half g_wol[D_MODEL * D_MODEL];
__device__ __align__(256) __half g_qh[BATCH * NH * SEQ * DK];   // [bh][s][dk], pre-scaled
__device__ __align__(256) __half g_kh[BATCH * NH * SEQ * DK];
__device__ __align__(256) __half g_vh[BATCH * NH * SEQ * DK];
__device__ __align__(256) __half g_ah[M_ROWS * D_MODEL];        // attn out

// ---------------- PTX helpers (base sm_80+ ISA only) ------------------------
__device__ __forceinline__ uint32_t smem_u32(const void* p) {
    uint32_t a;
    asm("{ .reg .u64 t; cvta.to.shared.u64 t, %1; cvt.u32.u64 %0, t; }"
        : "=r"(a) : "l"(p));
    return a;
}
#define SWZ128(off) ((off) ^ (((off) >> 3) & 0x70))

__device__ __forceinline__ uint32_t h2_as_u32(__half2 h) {
    union { __half2 h; uint32_t u; } c;
    c.h = h;
    return c.u;
}

__device__ __forceinline__ void cp_async16(uint32_t smem, const void* gmem) {
    asm volatile("cp.async.cg.shared.global [%0], [%1], 16;"
                 :: "r"(smem), "l"(gmem) : "memory");
}
#define CP_COMMIT() asm volatile("cp.async.commit_group;" ::: "memory")
#define CP_WAIT_1() asm volatile("cp.async.wait_group 1;" ::: "memory")

__device__ __forceinline__ void ldsm4(uint32_t* r, uint32_t a) {
    asm volatile("ldmatrix.sync.aligned.m8n8.x4.shared.b16 {%0,%1,%2,%3}, [%4];"
                 : "=r"(r[0]), "=r"(r[1]), "=r"(r[2]), "=r"(r[3]) : "r"(a));
}
__device__ __forceinline__ void ldsm4t(uint32_t* r, uint32_t a) {
    asm volatile("ldmatrix.sync.aligned.m8n8.x4.trans.shared.b16 {%0,%1,%2,%3}, [%4];"
                 : "=r"(r[0]), "=r"(r[1]), "=r"(r[2]), "=r"(r[3]) : "r"(a));
}
__device__ __forceinline__ void mma16816(float* c, const uint32_t* a, const uint32_t* b) {
    asm volatile(
        "mma.sync.aligned.m16n8k16.row.col.f32.f16.f16.f32 "
        "{%0,%1,%2,%3},{%4,%5,%6,%7},{%8,%9},{%0,%1,%2,%3};"
        : "+f"(c[0]), "+f"(c[1]), "+f"(c[2]), "+f"(c[3])
        : "r"(a[0]), "r"(a[1]), "r"(a[2]), "r"(a[3]), "r"(b[0]), "r"(b[1]));
}

// ---------------- conversion kernels -----------------------------------------
__global__ void cvt_hi(const float* __restrict__ s, __half* __restrict__ hi, int n4) {
    int i = blockIdx.x * blockDim.x + threadIdx.x;
    if (i >= n4) return;
    float4 v = ((const float4*)s)[i];
    ((__half2*)hi)[2 * i + 0] = __floats2half2_rn(v.x, v.y);
    ((__half2*)hi)[2 * i + 1] = __floats2half2_rn(v.z, v.w);
}

__global__ void cvt_split(const float* __restrict__ s, __half* __restrict__ hi,
                          __half* __restrict__ lo, int n4) {
    int i = blockIdx.x * blockDim.x + threadIdx.x;
    if (i >= n4) return;
    float4 v = ((const float4*)s)[i];
    __half h0 = __float2half_rn(v.x), h1 = __float2half_rn(v.y);
    __half h2 = __float2half_rn(v.z), h3 = __float2half_rn(v.w);
    ((__half2*)hi)[2 * i + 0] = __halves2half2(h0, h1);
    ((__half2*)hi)[2 * i + 1] = __halves2half2(h2, h3);
    ((__half2*)lo)[2 * i + 0] = __halves2half2(
        __float2half_rn(v.x - __half2float(h0)), __float2half_rn(v.y - __half2float(h1)));
    ((__half2*)lo)[2 * i + 1] = __halves2half2(
        __float2half_rn(v.z - __half2float(h2)), __float2half_rn(v.w - __half2float(h3)));
}

// ---------------- HMMA GEMM body: dst = A @ (Bh+Bl)^T + bias -----------------
// A:[4096,1024] fp16, B hi/lo:[1024,1024] fp16, K-contiguous. BM=BN=128, BK=64.
// Stage: A 16KB + Bh 16KB + Bl 16KB = 48KB; double-buffered (96KB).
// mode 0: Q -> g_qh (heads, scaled)  1: K -> g_kh  2: V -> g_vh  3: fp32 dst
#define GSTAGE_B 49152
#define GEMM_SMEM (2 * GSTAGE_B)              // 96KB

__device__ __forceinline__ void g_ldchunk(const __half* __restrict__ Ap,
                                          const __half* __restrict__ Bhp,
                                          const __half* __restrict__ Blp,
                                          int m0, int n0, int j, uint32_t sb, int tid) {
    const __half* ab  = Ap  + (size_t)m0 * D_MODEL + j * 64;
    const __half* bhb = Bhp + (size_t)n0 * D_MODEL + j * 64;
    const __half* blb = Blp + (size_t)n0 * D_MODEL + j * 64;
#pragma unroll
    for (int i = 0; i < 4; i++) {
        int c = i * 256 + tid;
        int row = c >> 3, q = c & 7;
        uint32_t so = SWZ128((uint32_t)(row * 128 + q * 16));
        size_t go = (size_t)row * D_MODEL + q * 8;
        cp_async16(sb + so, ab + go);
        cp_async16(sb + 16384 + so, bhb + go);
        cp_async16(sb + 32768 + so, blb + go);
    }
}

__device__ __forceinline__ void gemm_body(
    const __half* __restrict__ A, const __half* __restrict__ Bh,
    const __half* __restrict__ Bl, const float* __restrict__ bias,
    float* __restrict__ dst, int mode, char* smem)
{
    const uint32_t sbase = smem_u32(smem);
    const int tid = threadIdx.x;
    const int lane = tid & 31;
    const int wid = tid >> 5;
    const int wm = (wid >> 2) * 64;
    const int wn = (wid & 3) * 32;
    const int m0 = blockIdx.y * 128;
    const int n0 = blockIdx.x * 128;

    float acc[4][4][4] = {};

    g_ldchunk(A, Bh, Bl, m0, n0, 0, sbase, tid);
    CP_COMMIT();

    const int NG = 16;
    for (int g = 0; g < NG; g++) {
        if (g + 1 < NG)
            g_ldchunk(A, Bh, Bl, m0, n0, g + 1, sbase + ((g + 1) & 1) * GSTAGE_B, tid);
        CP_COMMIT();
        CP_WAIT_1();
        __syncthreads();

        uint32_t sA = sbase + (g & 1) * GSTAGE_B;
#pragma unroll
        for (int kk = 0; kk < 4; kk++) {
            uint32_t aF[4][4], bF[2][4];
#pragma unroll
            for (int mt = 0; mt < 4; mt++) {
                int row = wm + mt * 16 + (lane & 15);
                int kh = (lane >> 4);
                ldsm4(aF[mt], sA + SWZ128((uint32_t)(row * 128 + (kk * 16 + kh * 8) * 2)));
            }
            // Bh term
#pragma unroll
            for (int p = 0; p < 2; p++) {
                int row = wn + p * 16 + ((lane >> 4) << 3) + (lane & 7);
                int kh = (lane >> 3) & 1;
                ldsm4(bF[p], sA + 16384 +
                      SWZ128((uint32_t)(row * 128 + (kk * 16 + kh * 8) * 2)));
            }
#pragma unroll
            for (int mt = 0; mt < 4; mt++)
#pragma unroll
                for (int nt = 0; nt < 4; nt++)
                    mma16816(acc[mt][nt], aF[mt], &bF[nt >> 1][(nt & 1) * 2]);
            // Bl term (same A fragments)
#pragma unroll
            for (int p = 0; p < 2; p++) {
                int row = wn + p * 16 + ((lane >> 4) << 3) + (lane & 7);
                int kh = (lane >> 3) & 1;
                ldsm4(bF[p], sA + 32768 +
                      SWZ128((uint32_t)(row * 128 + (kk * 16 + kh * 8) * 2)));
            }
#pragma unroll
            for (int mt = 0; mt < 4; mt++)
#pragma unroll
                for (int nt = 0; nt < 4; nt++)
                    mma16816(acc[mt][nt], aF[mt], &bF[nt >> 1][(nt & 1) * 2]);
        }
        __syncthreads();
    }

    // epilogue
#pragma unroll
    for (int mt = 0; mt < 4; mt++) {
#pragma unroll
        for (int nt = 0; nt < 4; nt++) {
            int m = m0 + wm + mt * 16 + (lane >> 2);
            int n = n0 + wn + nt * 8 + 2 * (lane & 3);
            float b0 = bias[n], b1 = bias[n + 1];
#pragma unroll
            for (int half = 0; half < 2; half++) {
                int mm = m + half * 8;
                float v0 = acc[mt][nt][half * 2 + 0] + b0;
                float v1 = acc[mt][nt][half * 2 + 1] + b1;
                if (mode == 3) {
                    float2 o = {v0, v1};
                    *(float2*)(dst + (size_t)mm * D_MODEL + n) = o;
                } else {
                    int b = mm >> 11, s = mm & 2047;
                    int h = n >> 6, dd = n & 63;
                    size_t idx = (((size_t)(b * NH + h)) * SEQ + s) * DK + dd;
                    if (mode == 0) {
                        *(__half2*)(g_qh + idx) =
                            __floats2half2_rn(v0 * QSCALE, v1 * QSCALE);
                    } else if (mode == 1) {
                        *(__half2*)(g_kh + idx) = __floats2half2_rn(v0, v1);
                    } else {
                        *(__half2*)(g_vh + idx) = __floats2half2_rn(v0, v1);
                    }
                }
            }
        }
    }
}

// one launch for all three projections: blockIdx.z selects operands
__global__ void __launch_bounds__(256, 2) qkv_gemm(
    const __half* __restrict__ xq, const __half* __restrict__ xk,
    const __half* __restrict__ xv,
    const __half* __restrict__ wqh, const __half* __restrict__ wql,
    const __half* __restrict__ wkh, const __half* __restrict__ wkl,
    const __half* __restrict__ wvh, const __half* __restrict__ wvl,
    const float* __restrict__ bq, const float* __restrict__ bk,
    const float* __restrict__ bv)
{
    extern __shared__ char smem[];
    int z = blockIdx.z;
    const __half* A  = (z == 0) ? xq  : (z == 1) ? xk  : xv;
    const __half* Bh = (z == 0) ? wqh : (z == 1) ? wkh : wvh;
    const __half* Bl = (z == 0) ? wql : (z == 1) ? wkl : wvl;
    const float* bias = (z == 0) ? bq : (z == 1) ? bk : bv;
    gemm_body(A, Bh, Bl, bias, nullptr, z, smem);
}

__global__ void __launch_bounds__(256, 2) oproj_gemm(
    const __half* __restrict__ ah, const __half* __restrict__ woh,
    const __half* __restrict__ wol, const float* __restrict__ bo,
    float* __restrict__ dst)
{
    extern __shared__ char smem[];
    gemm_body(ah, woh, wol, bo, dst, 3, smem);
}

// ---------------- flash attention on mma.sync --------------------------------
// block = (qt [128 q rows], bh). 256 threads, 8 warps, warp owns 16 q rows.
// KV tiles of 64 keys, double-buffered. smem: Q 16KB + 2 x (K 8KB + V 8KB) = 48KB
#define ASTAGE_B 16384
#define ATTN_SMEM (16384 + 2 * ASTAGE_B)      // 48KB

__device__ __forceinline__ void a_ldkv(const __half* __restrict__ Kg,
                                       const __half* __restrict__ Vg,
                                       int kt, uint32_t sK, int tid) {
#pragma unroll
    for (int i = 0; i < 2; i++) {
        int c = i * 256 + tid;                 // 0..511
        int row = c >> 3, q = c & 7;
        uint32_t so = SWZ128((uint32_t)(row * 128 + q * 16));
        size_t go = (size_t)(kt * 64 + row) * DK + q * 8;
        cp_async16(sK + so, Kg + go);
        cp_async16(sK + 8192 + so, Vg + go);
    }
}

__global__ void __launch_bounds__(256, 2) attn_hmma()
{
    extern __shared__ char smem[];
    const uint32_t sbase = smem_u32(smem);
    const uint32_t sQ = sbase;
    const int tid = threadIdx.x;
    const int lane = tid & 31;
    const int wid = tid >> 5;
    const int qt = blockIdx.x;
    const int bh = blockIdx.y;
    const int m0 = wid * 16;

    const __half* Qg = g_qh + (size_t)bh * SEQ * DK;
    const __half* Kg = g_kh + (size_t)bh * SEQ * DK;
    const __half* Vg = g_vh + (size_t)bh * SEQ * DK;

#pragma unroll
    for (int i = 0; i < 4; i++) {
        int c = i * 256 + tid;
        int row = c >> 3, q = c & 7;
        cp_async16(sQ + SWZ128((uint32_t)(row * 128 + q * 16)),
                   Qg + (size_t)(qt * 128 + row) * DK + q * 8);
    }
    a_ldkv(Kg, Vg, 0, sbase + 16384, tid);
    CP_COMMIT();

    float oc[8][4] = {};
    float mst0 = -INFINITY, mst1 = -INFINITY;
    float lst0 = 0.f, lst1 = 0.f;

    for (int kt = 0; kt < SEQ / 64; kt++) {
        if (kt + 1 < SEQ / 64)
            a_ldkv(Kg, Vg, kt + 1, sbase + 16384 + ((kt + 1) & 1) * ASTAGE_B, tid);
        CP_COMMIT();
        CP_WAIT_1();
        __syncthreads();

        uint32_t sK = sbase + 16384 + (kt & 1) * ASTAGE_B;
        uint32_t sV = sK + 8192;

        // S = Qscaled @ K^T
        float sc[8][4] = {};
#pragma unroll
        for (int kk = 0; kk < 4; kk++) {
            uint32_t aQ[4], bK[4][4];
            {
                int row = m0 + (lane & 15);
                int kh = lane >> 4;
                ldsm4(aQ, sQ + SWZ128((uint32_t)(row * 128 + (kk * 16 + kh * 8) * 2)));
            }
#pragma unroll
            for (int p = 0; p < 4; p++) {
                int row = p * 16 + ((lane >> 4) << 3) + (lane & 7);
                int kh = (lane >> 3) & 1;
                ldsm4(bK[p], sK + SWZ128((uint32_t)(row * 128 + (kk * 16 + kh * 8) * 2)));
            }
#pragma unroll
            for (int nt = 0; nt < 8; nt++)
                mma16816(sc[nt], aQ, &bK[nt >> 1][(nt & 1) * 2]);
        }

        // online softmax (log2 domain)
        float mx0 = -INFINITY, mx1 = -INFINITY;
#pragma unroll
        for (int t = 0; t < 8; t++) {
            mx0 = fmaxf(mx0, fmaxf(sc[t][0], sc[t][1]));
            mx1 = fmaxf(mx1, fmaxf(sc[t][2], sc[t][3]));
        }
        mx0 = fmaxf(mx0, __shfl_xor_sync(0xffffffffu, mx0, 1));
        mx0 = fmaxf(mx0, __shfl_xor_sync(0xffffffffu, mx0, 2));
        mx1 = fmaxf(mx1, __shfl_xor_sync(0xffffffffu, mx1, 1));
        mx1 = fmaxf(mx1, __shfl_xor_sync(0xffffffffu, mx1, 2));
        float mn0 = fmaxf(mst0, mx0), mn1 = fmaxf(mst1, mx1);
        float c0 = exp2f(mst0 - mn0), c1 = exp2f(mst1 - mn1);
        mst0 = mn0; mst1 = mn1;
        float sum0 = 0.f, sum1 = 0.f;
#pragma unroll
        for (int t = 0; t < 8; t++) {
            sc[t][0] = exp2f(sc[t][0] - mn0); sum0 += sc[t][0];
            sc[t][1] = exp2f(sc[t][1] - mn0); sum0 += sc[t][1];
            sc[t][2] = exp2f(sc[t][2] - mn1); sum1 += sc[t][2];
            sc[t][3] = exp2f(sc[t][3] - mn1); sum1 += sc[t][3];
        }
        sum0 += __shfl_xor_sync(0xffffffffu, sum0, 1);
        sum0 += __shfl_xor_sync(0xffffffffu, sum0, 2);
        sum1 += __shfl_xor_sync(0xffffffffu, sum1, 1);
        sum1 += __shfl_xor_sync(0xffffffffu, sum1, 2);
        lst0 = lst0 * c0 + sum0;
        lst1 = lst1 * c1 + sum1;
#pragma unroll
        for (int t = 0; t < 8; t++) {
            oc[t][0] *= c0; oc[t][1] *= c0;
            oc[t][2] *= c1; oc[t][3] *= c1;
        }

        // O += P @ V
#pragma unroll
        for (int kk = 0; kk < 4; kk++) {
            uint32_t pa[4];
            pa[0] = h2_as_u32(__floats2half2_rn(sc[2*kk][0],   sc[2*kk][1]));
            pa[1] = h2_as_u32(__floats2half2_rn(sc[2*kk][2],   sc[2*kk][3]));
            pa[2] = h2_as_u32(__floats2half2_rn(sc[2*kk+1][0], sc[2*kk+1][1]));
            pa[3] = h2_as_u32(__floats2half2_rn(sc[2*kk+1][2], sc[2*kk+1][3]));
            uint32_t bV[4][4];
#pragma unroll
            for (int p = 0; p < 4; p++) {
                int krow = kk * 16 + ((lane >> 3) & 1) * 8 + (lane & 7);
                int ncol = p * 16 + ((lane >> 4) << 3);
                ldsm4t(bV[p], sV + SWZ128((uint32_t)(krow * 128 + ncol * 2)));
            }
#pragma unroll
            for (int nt = 0; nt < 8; nt++)
                mma16816(oc[nt], pa, &bV[nt >> 1][(nt & 1) * 2]);
        }
        __syncthreads();
    }

    // normalize, write combined layout [b*s][h*64+dv]
    const int b = bh >> 4, h = bh & 15;
    const float inv0 = 1.0f / lst0, inv1 = 1.0f / lst1;
#pragma unroll
    for (int t = 0; t < 8; t++) {
        int dv = t * 8 + 2 * (lane & 3);
#pragma unroll
        for (int half = 0; half < 2; half++) {
            int r = qt * 128 + m0 + (lane >> 2) + half * 8;
            float inv = half ? inv1 : inv0;
            size_t idx = ((size_t)b * SEQ + r) * D_MODEL + h * DK + dv;
            *(__half2*)(g_ah + idx) = __floats2half2_rn(
                oc[t][half * 2 + 0] * inv, oc[t][half * 2 + 1] * inv);
        }
    }
}

// ---------------------------------------------------------------------------
extern "C" void kernel_launch(void* const* d_in, const int* in_sizes, int n_in,
                              void* d_out, int out_size)
{
    const float* query = (const float*)d_in[0];
    const float* key   = (const float*)d_in[1];
    const float* value = (const float*)d_in[2];
    const float* Wq    = (const float*)d_in[3];
    const float* bq    = (const float*)d_in[4];
    const float* Wk    = (const float*)d_in[5];
    const float* bk    = (const float*)d_in[6];
    const float* Wv    = (const float*)d_in[7];
    const float* bv    = (const float*)d_in[8];
    const float* Wo    = (const float*)d_in[9];
    const float* bo    = (const float*)d_in[10];

    __half *xq, *xk, *xv;
    __half *wqh, *wql, *wkh, *wkl, *wvh, *wvl, *woh, *wol, *ah;
    cudaGetSymbolAddress((void**)&xq, g_xq);
    cudaGetSymbolAddress((void**)&xk, g_xk);
    cudaGetSymbolAddress((void**)&xv, g_xv);
    cudaGetSymbolAddress((void**)&wqh, g_wqh);
    cudaGetSymbolAddress((void**)&wql, g_wql);
    cudaGetSymbolAddress((void**)&wkh, g_wkh);
    cudaGetSymbolAddress((void**)&wkl, g_wkl);
    cudaGetSymbolAddress((void**)&wvh, g_wvh);
    cudaGetSymbolAddress((void**)&wvl, g_wvl);
    cudaGetSymbolAddress((void**)&woh, g_woh);
    cudaGetSymbolAddress((void**)&wol, g_wol);
    cudaGetSymbolAddress((void**)&ah, g_ah);

    const int nx4 = M_ROWS * D_MODEL / 4;
    const int nw4 = D_MODEL * D_MODEL / 4;
    cvt_hi<<<nx4 / 256, 256>>>(query, xq, nx4);
    cvt_hi<<<nx4 / 256, 256>>>(key,   xk, nx4);
    cvt_hi<<<nx4 / 256, 256>>>(value, xv, nx4);
    cvt_split<<<nw4 / 256, 256>>>(Wq, wqh, wql, nw4);
    cvt_split<<<nw4 / 256, 256>>>(Wk, wkh, wkl, nw4);
    cvt_split<<<nw4 / 256, 256>>>(Wv, wvh, wvl, nw4);
    cvt_split<<<nw4 / 256, 256>>>(Wo, woh, wol, nw4);

    cudaFuncSetAttribute(qkv_gemm, cudaFuncAttributeMaxDynamicSharedMemorySize,
                         GEMM_SMEM);
    cudaFuncSetAttribute(oproj_gemm, cudaFuncAttributeMaxDynamicSharedMemorySize,
                         GEMM_SMEM);
    cudaFuncSetAttribute(attn_hmma, cudaFuncAttributeMaxDynamicSharedMemorySize,
                         ATTN_SMEM);

    dim3 qkvgrid(D_MODEL / 128, M_ROWS / 128, 3);   // (8, 32, 3)
    qkv_gemm<<<qkvgrid, 256, GEMM_SMEM>>>(xq, xk, xv, wqh, wql, wkh, wkl,
                                          wvh, wvl, bq, bk, bv);

    attn_hmma<<<dim3(SEQ / 128, BATCH * NH), 256, ATTN_SMEM>>>();

    dim3 ogrid(D_MODEL / 128, M_ROWS / 128);        // (8, 32)
    oproj_gemm<<<ogrid, 256, GEMM_SMEM>>>(ah, woh, wol, bo, (float*)d_out);
}

// round 6
// speedup vs baseline: 7.5578x; 1.3495x over previous
#include <cuda_runtime.h>
#include <cuda_fp16.h>
#include <math.h>
#include <stdint.h>

#define D_MODEL 1024
#define SEQ     2048
#define BATCH   2
#define NH      16
#define DK      64
#define M_ROWS  (BATCH * SEQ)          // 4096
#define QSCALE  (0.125f * 1.44269504088896f)   // 1/sqrt(64) * log2(e)

// ---------------- scratch (static device globals; no allocation) ------------
__device__ __align__(256) __half g_xq[M_ROWS * D_MODEL];        // fp16 inputs
__device__ __align__(256) __half g_xk[M_ROWS * D_MODEL];
__device__ __align__(256) __half g_xv[M_ROWS * D_MODEL];
__device__ __align__(256) __half g_wq[D_MODEL * D_MODEL];       // fp16 weights
__device__ __align__(256) __half g_wk[D_MODEL * D_MODEL];
__device__ __align__(256) __half g_wv[D_MODEL * D_MODEL];
__device__ __align__(256) __half g_wo[D_MODEL * D_MODEL];
__device__ __align__(256) __half g_qh[BATCH * NH * SEQ * DK];   // [bh][s][dk], pre-scaled
__device__ __align__(256) __half g_kh[BATCH * NH * SEQ * DK];
__device__ __align__(256) __half g_vh[BATCH * NH * SEQ * DK];
__device__ __align__(256) __half g_ah[M_ROWS * D_MODEL];        // attn out

// ---------------- PTX helpers (base sm_80+ ISA only) ------------------------
__device__ __forceinline__ uint32_t smem_u32(const void* p) {
    uint32_t a;
    asm("{ .reg .u64 t; cvta.to.shared.u64 t, %1; cvt.u32.u64 %0, t; }"
        : "=r"(a) : "l"(p));
    return a;
}
#define SWZ128(off) ((off) ^ (((off) >> 3) & 0x70))

__device__ __forceinline__ uint32_t h2_as_u32(__half2 h) {
    union { __half2 h; uint32_t u; } c;
    c.h = h;
    return c.u;
}

__device__ __forceinline__ void cp_async16(uint32_t smem, const void* gmem) {
    asm volatile("cp.async.cg.shared.global [%0], [%1], 16;"
                 :: "r"(smem), "l"(gmem) : "memory");
}
#define CP_COMMIT() asm volatile("cp.async.commit_group;" ::: "memory")
#define CP_WAIT_0() asm volatile("cp.async.wait_group 0;" ::: "memory")

__device__ __forceinline__ void ldsm4(uint32_t* r, uint32_t a) {
    asm volatile("ldmatrix.sync.aligned.m8n8.x4.shared.b16 {%0,%1,%2,%3}, [%4];"
                 : "=r"(r[0]), "=r"(r[1]), "=r"(r[2]), "=r"(r[3]) : "r"(a));
}
__device__ __forceinline__ void ldsm4t(uint32_t* r, uint32_t a) {
    asm volatile("ldmatrix.sync.aligned.m8n8.x4.trans.shared.b16 {%0,%1,%2,%3}, [%4];"
                 : "=r"(r[0]), "=r"(r[1]), "=r"(r[2]), "=r"(r[3]) : "r"(a));
}
__device__ __forceinline__ void mma16816(float* c, const uint32_t* a, const uint32_t* b) {
    asm volatile(
        "mma.sync.aligned.m16n8k16.row.col.f32.f16.f16.f32 "
        "{%0,%1,%2,%3},{%4,%5,%6,%7},{%8,%9},{%0,%1,%2,%3};"
        : "+f"(c[0]), "+f"(c[1]), "+f"(c[2]), "+f"(c[3])
        : "r"(a[0]), "r"(a[1]), "r"(a[2]), "r"(a[3]), "r"(b[0]), "r"(b[1]));
}

// ---------------- conversion kernels (fused, 2 launches total) ---------------
__global__ void cvt_in(const float* __restrict__ q, const float* __restrict__ k,
                       const float* __restrict__ v, __half* __restrict__ xq,
                       __half* __restrict__ xk, __half* __restrict__ xv, int n4) {
    int z = blockIdx.y;
    const float* s = (z == 0) ? q : (z == 1) ? k : v;
    __half* d = (z == 0) ? xq : (z == 1) ? xk : xv;
    int i = blockIdx.x * blockDim.x + threadIdx.x;
    if (i >= n4) return;
    float4 w = ((const float4*)s)[i];
    ((__half2*)d)[2 * i + 0] = __floats2half2_rn(w.x, w.y);
    ((__half2*)d)[2 * i + 1] = __floats2half2_rn(w.z, w.w);
}

__global__ void cvt_w(const float* __restrict__ wq, const float* __restrict__ wk,
                      const float* __restrict__ wv, const float* __restrict__ wo,
                      __half* __restrict__ dq, __half* __restrict__ dk,
                      __half* __restrict__ dv, __half* __restrict__ dow, int n4) {
    int z = blockIdx.y;
    const float* s = (z == 0) ? wq : (z == 1) ? wk : (z == 2) ? wv : wo;
    __half* d = (z == 0) ? dq : (z == 1) ? dk : (z == 2) ? dv : dow;
    int i = blockIdx.x * blockDim.x + threadIdx.x;
    if (i >= n4) return;
    float4 w = ((const float4*)s)[i];
    ((__half2*)d)[2 * i + 0] = __floats2half2_rn(w.x, w.y);
    ((__half2*)d)[2 * i + 1] = __floats2half2_rn(w.z, w.w);
}

// ---------------- HMMA GEMM body: dst = A @ B^T + bias -----------------------
// A:[4096,1024] fp16, B:[1024,1024] fp16, K-contiguous. BM=BN=128, BK=64.
// Stage: A 16KB + B 16KB = 32KB; double-buffered (64KB).
// mode 0: Q -> g_qh (heads, scaled)  1: K -> g_kh  2: V -> g_vh  3: fp32 dst
#define GSTAGE_B 32768
#define GEMM_SMEM (2 * GSTAGE_B)              // 64KB

__device__ __forceinline__ void g_ldchunk(const __half* __restrict__ Ap,
                                          const __half* __restrict__ Bp,
                                          int m0, int n0, int j, uint32_t sb, int tid) {
    const __half* ab = Ap + (size_t)m0 * D_MODEL + j * 64;
    const __half* bb = Bp + (size_t)n0 * D_MODEL + j * 64;
#pragma unroll
    for (int i = 0; i < 4; i++) {
        int c = i * 256 + tid;
        int row = c >> 3, q = c & 7;
        uint32_t so = SWZ128((uint32_t)(row * 128 + q * 16));
        size_t go = (size_t)row * D_MODEL + q * 8;
        cp_async16(sb + so, ab + go);
        cp_async16(sb + 16384 + so, bb + go);
    }
}

__device__ __forceinline__ void gemm_body(
    const __half* __restrict__ A, const __half* __restrict__ B,
    const float* __restrict__ bias, float* __restrict__ dst, int mode, char* smem)
{
    const uint32_t sbase = smem_u32(smem);
    const int tid = threadIdx.x;
    const int lane = tid & 31;
    const int wid = tid >> 5;
    const int wm = (wid >> 2) * 64;
    const int wn = (wid & 3) * 32;
    const int m0 = blockIdx.y * 128;
    const int n0 = blockIdx.x * 128;

    float acc[4][4][4] = {};

    g_ldchunk(A, B, m0, n0, 0, sbase, tid);
    CP_COMMIT();

    const int NG = 16;
    for (int g = 0; g < NG; g++) {
        CP_WAIT_0();            // chunk g resident (only group outstanding)
        __syncthreads();        // visible to all warps; prev compute done
        if (g + 1 < NG) {
            g_ldchunk(A, B, m0, n0, g + 1, sbase + ((g + 1) & 1) * GSTAGE_B, tid);
            CP_COMMIT();
        }

        uint32_t sA = sbase + (g & 1) * GSTAGE_B;
        uint32_t sB = sA + 16384;
#pragma unroll
        for (int kk = 0; kk < 4; kk++) {
            uint32_t aF[4][4], bF[2][4];
#pragma unroll
            for (int mt = 0; mt < 4; mt++) {
                int row = wm + mt * 16 + (lane & 15);
                int kh = (lane >> 4);
                ldsm4(aF[mt], sA + SWZ128((uint32_t)(row * 128 + (kk * 16 + kh * 8) * 2)));
            }
#pragma unroll
            for (int p = 0; p < 2; p++) {
                int row = wn + p * 16 + ((lane >> 4) << 3) + (lane & 7);
                int kh = (lane >> 3) & 1;
                ldsm4(bF[p], sB + SWZ128((uint32_t)(row * 128 + (kk * 16 + kh * 8) * 2)));
            }
#pragma unroll
            for (int mt = 0; mt < 4; mt++)
#pragma unroll
                for (int nt = 0; nt < 4; nt++)
                    mma16816(acc[mt][nt], aF[mt], &bF[nt >> 1][(nt & 1) * 2]);
        }
    }

    // epilogue
#pragma unroll
    for (int mt = 0; mt < 4; mt++) {
#pragma unroll
        for (int nt = 0; nt < 4; nt++) {
            int m = m0 + wm + mt * 16 + (lane >> 2);
            int n = n0 + wn + nt * 8 + 2 * (lane & 3);
            float b0 = bias[n], b1 = bias[n + 1];
#pragma unroll
            for (int half = 0; half < 2; half++) {
                int mm = m + half * 8;
                float v0 = acc[mt][nt][half * 2 + 0] + b0;
                float v1 = acc[mt][nt][half * 2 + 1] + b1;
                if (mode == 3) {
                    float2 o = {v0, v1};
                    *(float2*)(dst + (size_t)mm * D_MODEL + n) = o;
                } else {
                    int b = mm >> 11, s = mm & 2047;
                    int h = n >> 6, dd = n & 63;
                    size_t idx = (((size_t)(b * NH + h)) * SEQ + s) * DK + dd;
                    if (mode == 0) {
                        *(__half2*)(g_qh + idx) =
                            __floats2half2_rn(v0 * QSCALE, v1 * QSCALE);
                    } else if (mode == 1) {
                        *(__half2*)(g_kh + idx) = __floats2half2_rn(v0, v1);
                    } else {
                        *(__half2*)(g_vh + idx) = __floats2half2_rn(v0, v1);
                    }
                }
            }
        }
    }
}

// one launch for all three projections: blockIdx.z selects operands
__global__ void __launch_bounds__(256, 2) qkv_gemm(
    const __half* __restrict__ xq, const __half* __restrict__ xk,
    const __half* __restrict__ xv,
    const __half* __restrict__ wq, const __half* __restrict__ wk,
    const __half* __restrict__ wv,
    const float* __restrict__ bq, const float* __restrict__ bk,
    const float* __restrict__ bv)
{
    extern __shared__ char smem[];
    int z = blockIdx.z;
    const __half* A = (z == 0) ? xq : (z == 1) ? xk : xv;
    const __half* B = (z == 0) ? wq : (z == 1) ? wk : wv;
    const float* bias = (z == 0) ? bq : (z == 1) ? bk : bv;
    gemm_body(A, B, bias, nullptr, z, smem);
}

__global__ void __launch_bounds__(256, 2) oproj_gemm(
    const __half* __restrict__ ah, const __half* __restrict__ wo,
    const float* __restrict__ bo, float* __restrict__ dst)
{
    extern __shared__ char smem[];
    gemm_body(ah, wo, bo, dst, 3, smem);
}

// ---------------- flash attention on mma.sync --------------------------------
// block = (qt [128 q rows], bh). 256 threads, 8 warps, warp owns 16 q rows.
// KV tiles of 64 keys, double-buffered. smem: Q 16KB + 2 x (K 8KB + V 8KB) = 48KB
#define ASTAGE_B 16384
#define ATTN_SMEM (16384 + 2 * ASTAGE_B)      // 48KB

__device__ __forceinline__ void a_ldkv(const __half* __restrict__ Kg,
                                       const __half* __restrict__ Vg,
                                       int kt, uint32_t sK, int tid) {
#pragma unroll
    for (int i = 0; i < 2; i++) {
        int c = i * 256 + tid;                 // 0..511
        int row = c >> 3, q = c & 7;
        uint32_t so = SWZ128((uint32_t)(row * 128 + q * 16));
        size_t go = (size_t)(kt * 64 + row) * DK + q * 8;
        cp_async16(sK + so, Kg + go);
        cp_async16(sK + 8192 + so, Vg + go);
    }
}

__global__ void __launch_bounds__(256, 2) attn_hmma()
{
    extern __shared__ char smem[];
    const uint32_t sbase = smem_u32(smem);
    const uint32_t sQ = sbase;
    const int tid = threadIdx.x;
    const int lane = tid & 31;
    const int wid = tid >> 5;
    const int qt = blockIdx.x;
    const int bh = blockIdx.y;
    const int m0 = wid * 16;

    const __half* Qg = g_qh + (size_t)bh * SEQ * DK;
    const __half* Kg = g_kh + (size_t)bh * SEQ * DK;
    const __half* Vg = g_vh + (size_t)bh * SEQ * DK;

#pragma unroll
    for (int i = 0; i < 4; i++) {
        int c = i * 256 + tid;
        int row = c >> 3, q = c & 7;
        cp_async16(sQ + SWZ128((uint32_t)(row * 128 + q * 16)),
                   Qg + (size_t)(qt * 128 + row) * DK + q * 8);
    }
    a_ldkv(Kg, Vg, 0, sbase + 16384, tid);
    CP_COMMIT();

    uint32_t aQ[4][4];           // hoisted Q fragments (iteration-invariant)
    float oc[8][4] = {};
    float mst0 = -INFINITY, mst1 = -INFINITY;
    float lst0 = 0.f, lst1 = 0.f;

    const int NT = SEQ / 64;
    for (int kt = 0; kt < NT; kt++) {
        CP_WAIT_0();
        __syncthreads();
        if (kt + 1 < NT) {
            a_ldkv(Kg, Vg, kt + 1, sbase + 16384 + ((kt + 1) & 1) * ASTAGE_B, tid);
            CP_COMMIT();
        }
        if (kt == 0) {
#pragma unroll
            for (int kk = 0; kk < 4; kk++) {
                int row = m0 + (lane & 15);
                int kh = lane >> 4;
                ldsm4(aQ[kk], sQ + SWZ128((uint32_t)(row * 128 + (kk * 16 + kh * 8) * 2)));
            }
        }

        uint32_t sK = sbase + 16384 + (kt & 1) * ASTAGE_B;
        uint32_t sV = sK + 8192;

        // S = Qscaled @ K^T
        float sc[8][4] = {};
#pragma unroll
        for (int kk = 0; kk < 4; kk++) {
            uint32_t bK[4][4];
#pragma unroll
            for (int p = 0; p < 4; p++) {
                int row = p * 16 + ((lane >> 4) << 3) + (lane & 7);
                int kh = (lane >> 3) & 1;
                ldsm4(bK[p], sK + SWZ128((uint32_t)(row * 128 + (kk * 16 + kh * 8) * 2)));
            }
#pragma unroll
            for (int nt = 0; nt < 8; nt++)
                mma16816(sc[nt], aQ[kk], &bK[nt >> 1][(nt & 1) * 2]);
        }

        // online softmax (log2 domain)
        float mx0 = -INFINITY, mx1 = -INFINITY;
#pragma unroll
        for (int t = 0; t < 8; t++) {
            mx0 = fmaxf(mx0, fmaxf(sc[t][0], sc[t][1]));
            mx1 = fmaxf(mx1, fmaxf(sc[t][2], sc[t][3]));
        }
        mx0 = fmaxf(mx0, __shfl_xor_sync(0xffffffffu, mx0, 1));
        mx0 = fmaxf(mx0, __shfl_xor_sync(0xffffffffu, mx0, 2));
        mx1 = fmaxf(mx1, __shfl_xor_sync(0xffffffffu, mx1, 1));
        mx1 = fmaxf(mx1, __shfl_xor_sync(0xffffffffu, mx1, 2));
        float mn0 = fmaxf(mst0, mx0), mn1 = fmaxf(mst1, mx1);
        float c0 = exp2f(mst0 - mn0), c1 = exp2f(mst1 - mn1);
        mst0 = mn0; mst1 = mn1;
        float sum0 = 0.f, sum1 = 0.f;
#pragma unroll
        for (int t = 0; t < 8; t++) {
            sc[t][0] = exp2f(sc[t][0] - mn0); sum0 += sc[t][0];
            sc[t][1] = exp2f(sc[t][1] - mn0); sum0 += sc[t][1];
            sc[t][2] = exp2f(sc[t][2] - mn1); sum1 += sc[t][2];
            sc[t][3] = exp2f(sc[t][3] - mn1); sum1 += sc[t][3];
        }
        sum0 += __shfl_xor_sync(0xffffffffu, sum0, 1);
        sum0 += __shfl_xor_sync(0xffffffffu, sum0, 2);
        sum1 += __shfl_xor_sync(0xffffffffu, sum1, 1);
        sum1 += __shfl_xor_sync(0xffffffffu, sum1, 2);
        lst0 = lst0 * c0 + sum0;
        lst1 = lst1 * c1 + sum1;
#pragma unroll
        for (int t = 0; t < 8; t++) {
            oc[t][0] *= c0; oc[t][1] *= c0;
            oc[t][2] *= c1; oc[t][3] *= c1;
        }

        // O += P @ V
#pragma unroll
        for (int kk = 0; kk < 4; kk++) {
            uint32_t pa[4];
            pa[0] = h2_as_u32(__floats2half2_rn(sc[2*kk][0],   sc[2*kk][1]));
            pa[1] = h2_as_u32(__floats2half2_rn(sc[2*kk][2],   sc[2*kk][3]));
            pa[2] = h2_as_u32(__floats2half2_rn(sc[2*kk+1][0], sc[2*kk+1][1]));
            pa[3] = h2_as_u32(__floats2half2_rn(sc[2*kk+1][2], sc[2*kk+1][3]));
            uint32_t bV[4][4];
#pragma unroll
            for (int p = 0; p < 4; p++) {
                int krow = kk * 16 + ((lane >> 3) & 1) * 8 + (lane & 7);
                int ncol = p * 16 + ((lane >> 4) << 3);
                ldsm4t(bV[p], sV + SWZ128((uint32_t)(krow * 128 + ncol * 2)));
            }
#pragma unroll
            for (int nt = 0; nt < 8; nt++)
                mma16816(oc[nt], pa, &bV[nt >> 1][(nt & 1) * 2]);
        }
    }

    // normalize, write combined layout [b*s][h*64+dv]
    const int b = bh >> 4, h = bh & 15;
    const float inv0 = 1.0f / lst0, inv1 = 1.0f / lst1;
#pragma unroll
    for (int t = 0; t < 8; t++) {
        int dv = t * 8 + 2 * (lane & 3);
#pragma unroll
        for (int half = 0; half < 2; half++) {
            int r = qt * 128 + m0 + (lane >> 2) + half * 8;
            float inv = half ? inv1 : inv0;
            size_t idx = ((size_t)b * SEQ + r) * D_MODEL + h * DK + dv;
            *(__half2*)(g_ah + idx) = __floats2half2_rn(
                oc[t][half * 2 + 0] * inv, oc[t][half * 2 + 1] * inv);
        }
    }
}

// ---------------------------------------------------------------------------
extern "C" void kernel_launch(void* const* d_in, const int* in_sizes, int n_in,
                              void* d_out, int out_size)
{
    const float* query = (const float*)d_in[0];
    const float* key   = (const float*)d_in[1];
    const float* value = (const float*)d_in[2];
    const float* Wq    = (const float*)d_in[3];
    const float* bq    = (const float*)d_in[4];
    const float* Wk    = (const float*)d_in[5];
    const float* bk    = (const float*)d_in[6];
    const float* Wv    = (const float*)d_in[7];
    const float* bv    = (const float*)d_in[8];
    const float* Wo    = (const float*)d_in[9];
    const float* bo    = (const float*)d_in[10];

    __half *xq, *xk, *xv, *wq, *wk, *wv, *wo, *ah;
    cudaGetSymbolAddress((void**)&xq, g_xq);
    cudaGetSymbolAddress((void**)&xk, g_xk);
    cudaGetSymbolAddress((void**)&xv, g_xv);
    cudaGetSymbolAddress((void**)&wq, g_wq);
    cudaGetSymbolAddress((void**)&wk, g_wk);
    cudaGetSymbolAddress((void**)&wv, g_wv);
    cudaGetSymbolAddress((void**)&wo, g_wo);
    cudaGetSymbolAddress((void**)&ah, g_ah);

    const int nx4 = M_ROWS * D_MODEL / 4;        // 1,048,576
    const int nw4 = D_MODEL * D_MODEL / 4;       // 262,144
    cvt_in<<<dim3(nx4 / 256, 3), 256>>>(query, key, value, xq, xk, xv, nx4);
    cvt_w<<<dim3(nw4 / 256, 4), 256>>>(Wq, Wk, Wv, Wo, wq, wk, wv, wo, nw4);

    cudaFuncSetAttribute(qkv_gemm, cudaFuncAttributeMaxDynamicSharedMemorySize,
                         GEMM_SMEM);
    cudaFuncSetAttribute(oproj_gemm, cudaFuncAttributeMaxDynamicSharedMemorySize,
                         GEMM_SMEM);
    cudaFuncSetAttribute(attn_hmma, cudaFuncAttributeMaxDynamicSharedMemorySize,
                         ATTN_SMEM);

    dim3 qkvgrid(D_MODEL / 128, M_ROWS / 128, 3);   // (8, 32, 3)
    qkv_gemm<<<qkvgrid, 256, GEMM_SMEM>>>(xq, xk, xv, wq, wk, wv, bq, bk, bv);

    attn_hmma<<<dim3(SEQ / 128, BATCH * NH), 256, ATTN_SMEM>>>();

    dim3 ogrid(D_MODEL / 128, M_ROWS / 128);        // (8, 32)
    oproj_gemm<<<ogrid, 256, GEMM_SMEM>>>(ah, wo, bo, (float*)d_out);
}